// round 3
// baseline (speedup 1.0000x reference)
#include <cuda_runtime.h>
#include <cstdint>

#define BB 8
#define CH 256
#define HH 128
#define WW 128
#define NPIX (BB*HH*WW)

// ---------------- scratch (allocation-free) ----------------
__device__ unsigned char g_act[(size_t)NPIX*CH];   // 33.5 MB NHWC s8 of binarize(x)
__device__ unsigned char g_mid[(size_t)NPIX*CH];   // 33.5 MB NHWC s8 of binarize(prelu(concat))
__device__ unsigned char g_wbr[4*5*64*CH];         // [br][k][o][c] s8
__device__ unsigned char g_wmc[9*CH*CH];           // [t][o][c] s8

// ---------------- PTX helpers ----------------
__device__ __forceinline__ unsigned smem_u32(const void* p) {
    return (unsigned)__cvta_generic_to_shared(p);
}
__device__ __forceinline__ void cp16(unsigned s, const void* g, bool v) {
    int sz = v ? 16 : 0;
    asm volatile("cp.async.cg.shared.global [%0], [%1], 16, %2;" :: "r"(s), "l"(g), "r"(sz));
}
__device__ __forceinline__ void cp_commit() { asm volatile("cp.async.commit_group;"); }
template<int N> __device__ __forceinline__ void cp_wait() {
    asm volatile("cp.async.wait_group %0;" :: "n"(N));
}
__device__ __forceinline__ void ldsm4(unsigned &r0, unsigned &r1, unsigned &r2, unsigned &r3, unsigned a) {
    asm volatile("ldmatrix.sync.aligned.m8n8.x4.shared.b16 {%0,%1,%2,%3}, [%4];"
        : "=r"(r0), "=r"(r1), "=r"(r2), "=r"(r3) : "r"(a));
}
__device__ __forceinline__ void mma8(int* d, unsigned a0, unsigned a1, unsigned a2, unsigned a3,
                                     unsigned b0, unsigned b1) {
    asm volatile("mma.sync.aligned.m16n8k32.row.col.s32.s8.s8.s32 "
        "{%0,%1,%2,%3}, {%4,%5,%6,%7}, {%8,%9}, {%0,%1,%2,%3};"
        : "+r"(d[0]), "+r"(d[1]), "+r"(d[2]), "+r"(d[3])
        : "r"(a0), "r"(a1), "r"(a2), "r"(a3), "r"(b0), "r"(b1));
}

// ---------------------------------------------------------------------------
// binarize(x): NCHW f32 -> NHWC s8 (+1/-1) via smem transpose. 32 px/block.
__global__ __launch_bounds__(256) void pack_acts(const float* __restrict__ x) {
    __shared__ unsigned char buf[32*264];
    const int pix0 = blockIdx.x * 32;
    const int b = pix0 >> 14, hw0 = pix0 & 16383;
    const int t = threadIdx.x;
    const float* xb = x + (size_t)b * CH * 16384 + hw0;
    #pragma unroll
    for (int it = 0; it < 32; it++) {
        int idx = it*256 + t;
        int c = idx >> 5, p = idx & 31;
        float v = xb[(size_t)c * 16384 + p];
        buf[p*264 + c] = (v >= 0.f) ? 0x01 : 0xFF;
    }
    __syncthreads();
    unsigned* dst = (unsigned*)(g_act + (size_t)pix0 * CH);
    #pragma unroll
    for (int it = 0; it < 8; it++) {
        int j = it*256 + t;
        int p = j >> 6, wd = j & 63;
        dst[p*64 + wd] = *(const unsigned*)(buf + p*264 + wd*4);
    }
}

// ---------------------------------------------------------------------------
// binarize weights -> s8, reorder to [tap][o][c]
__global__ __launch_bounds__(256) void pack_wts(
    const float* __restrict__ w1, const float* __restrict__ w2,
    const float* __restrict__ w3, const float* __restrict__ w4,
    const float* __restrict__ wc)
{
    int gid = blockIdx.x*256 + threadIdx.x;
    if (gid < 4*5*64*64) {
        int c4 = gid & 63, o = (gid >> 6) & 63, kk = gid >> 12;
        int k = kk % 5, br = kk / 5;
        const float* src = (br==0) ? w1 : (br==1) ? w2 : (br==2) ? w3 : w4;
        unsigned wv = 0;
        #pragma unroll
        for (int i = 0; i < 4; i++) {
            float v = src[(o*CH + c4*4 + i)*5 + k];
            wv |= (unsigned)((v >= 0.f) ? 0x01u : 0xFFu) << (i*8);
        }
        ((unsigned*)g_wbr)[gid] = wv;
    } else {
        int j = gid - 4*5*64*64;
        if (j < 9*CH*64) {
            int c4 = j & 63, o = (j >> 6) & 255, tt = j >> 14;
            unsigned wv = 0;
            #pragma unroll
            for (int i = 0; i < 4; i++) {
                float v = wc[(o*CH + c4*4 + i)*9 + tt];
                wv |= (unsigned)((v >= 0.f) ? 0x01u : 0xFFu) << (i*8);
            }
            ((unsigned*)g_wmc)[j] = wv;
        }
    }
}

// ---------------------------------------------------------------------------
// Branch GEMMs. Block = (row, branch). M=128 px, N=64, K=5 taps x 256.
// 8 warps, warp tile m16 x n64. Double-buffered cp.async stages:
// stage s at s*49152: [A 32768][B 16384]. Epilogue staging reuses offset 0.
__global__ __launch_bounds__(256, 2) void branch_gemm(
    const float* __restrict__ b1, const float* __restrict__ b2,
    const float* __restrict__ b3, const float* __restrict__ b4,
    const float* __restrict__ a1p)
{
    extern __shared__ unsigned char sm[];
    const int rowid = blockIdx.x >> 2, br = blockIdx.x & 3;
    const int b = rowid >> 7, h = rowid & 127;
    const int tid = threadIdx.x, warp = tid >> 5, lane = tid & 31;
    const int m0 = warp * 16;

    auto load_stage = [&](int k, int s) {
        int d = k - 2, dh = 0, dw = 0;
        if (br == 0) dw = d; else if (br == 1) dw = 2*d;
        else if (br == 2) dh = d; else dh = 2*d;
        unsigned aB = smem_u32(sm + s*49152);
        unsigned bB = aB + 32768;
        int hs = h + dh;
        bool hv = (hs >= 0 && hs < HH);
        int hsc = hv ? hs : 0;
        const unsigned char* arow = g_act + ((size_t)(b*HH + hsc) * WW) * CH;
        #pragma unroll
        for (int i = 0; i < 8; i++) {                 // A: 2048 16B chunks
            int idx = i*256 + tid;
            int px = idx >> 4, ch = idx & 15;
            int ws = px + dw;
            bool v = hv && (ws >= 0) && (ws < WW);
            int wsc = (ws >= 0 && ws < WW) ? ws : 0;
            cp16(aB + px*256 + ((ch ^ (px & 7)) << 4), arow + (size_t)wsc*CH + ch*16, v);
        }
        const unsigned char* bsrc = g_wbr + ((size_t)((br*5 + k)*64)) * CH;
        #pragma unroll
        for (int i = 0; i < 4; i++) {                 // B: 1024 chunks
            int idx = i*256 + tid;
            int o = idx >> 4, ch = idx & 15;
            cp16(bB + o*256 + ((ch ^ (o & 7)) << 4), bsrc + (size_t)o*CH + ch*16, true);
        }
    };

    int acc[8][4];
    #pragma unroll
    for (int i = 0; i < 8; i++)
        #pragma unroll
        for (int j = 0; j < 4; j++) acc[i][j] = 0;

    load_stage(0, 0);
    cp_commit();

    const int a_row = lane & 15;
    const int a_kx  = (lane >> 4) & 1;
    const int b_row = (lane & 7) + ((lane >> 4) & 1) * 8;
    const int b_kx  = (lane >> 3) & 1;

    for (int k = 0; k < 5; k++) {
        if (k < 4) load_stage(k + 1, (k + 1) & 1);
        cp_commit();
        cp_wait<1>();
        __syncthreads();
        unsigned aB = smem_u32(sm + (k & 1)*49152);
        unsigned bB = aB + 32768;
        int p = m0 + a_row;
        #pragma unroll
        for (int ks = 0; ks < 8; ks++) {
            unsigned a0, a1_, a2, a3;
            ldsm4(a0, a1_, a2, a3, aB + p*256 + (((2*ks + a_kx) ^ (p & 7)) << 4));
            #pragma unroll
            for (int bt = 0; bt < 4; bt++) {
                unsigned r0, r1, r2, r3;
                int o = bt*16 + b_row;
                ldsm4(r0, r1, r2, r3, bB + o*256 + (((2*ks + b_kx) ^ (o & 7)) << 4));
                mma8(acc[2*bt],     a0, a1_, a2, a3, r0, r1);
                mma8(acc[2*bt + 1], a0, a1_, a2, a3, r2, r3);
            }
        }
        __syncthreads();
    }
    cp_wait<0>();
    __syncthreads();

    // epilogue: bias + prelu sign -> s8, stage, coalesced store
    const float* bp = (br==0) ? b1 : (br==1) ? b2 : (br==2) ? b3 : b4;
    const float a1v = a1p[0];
    unsigned char* st = sm;                           // 128 x 64 s8
    #pragma unroll
    for (int nt = 0; nt < 8; nt++)
        #pragma unroll
        for (int di = 0; di < 4; di++) {
            int px  = m0 + (lane >> 2) + 8*(di >> 1);
            int chl = nt*8 + (lane & 3)*2 + (di & 1);
            float v  = (float)acc[nt][di] + __ldg(bp + chl);
            float pr = (v >= 0.f) ? v : a1v * v;
            st[px*64 + chl] = (pr >= 0.f) ? 0x01 : 0xFF;
        }
    __syncthreads();
    unsigned char* dstBase = g_mid + (size_t)rowid * WW * CH + br*64;
    #pragma unroll
    for (int i = 0; i < 2; i++) {
        int idx = i*256 + tid;                        // 512 uint4
        int px = idx >> 2, cq = idx & 3;
        *(uint4*)(dstBase + (size_t)px*CH + cq*16) = *(const uint4*)(st + px*64 + cq*16);
    }
}

// ---------------------------------------------------------------------------
// Main 3x3 GEMM + bias + prelu + residual. Block = (row, N-half).
// M=128 px, N=128, K=9 taps x 256. 8 warps, warp tile m32 x n64.
// smem: [0,99840) = 3 halo row buffers (130 px x 256, reused by all taps);
//       B tap tiles double-buffered at 99840 + s*32768. Epilogue reuses [0,..).
#define RBSTRIDE (130*256)
__global__ __launch_bounds__(256) void main_gemm(
    const float* __restrict__ x, const float* __restrict__ bc,
    const float* __restrict__ a2p, float* __restrict__ out)
{
    extern __shared__ unsigned char sm[];
    const int rowid = blockIdx.x >> 1, nh = blockIdx.x & 1;
    const int b = rowid >> 7, h = rowid & 127;
    const int tid = threadIdx.x, warp = tid >> 5, lane = tid & 31;
    const int m0 = (warp & 3) * 32;
    const int n0 = (warp >> 2) * 64;

    {   // prologue: 3 halo row buffers from g_mid
        const unsigned rb = smem_u32(sm);
        for (int i = tid; i < 6240; i += 256) {       // 3 * 130 * 16 chunks
            int r = i / 2080, rem = i - r*2080;
            int p = rem >> 4, ch = rem & 15;
            int hs = h - 1 + r, ws = p - 1;
            bool v = (hs >= 0 && hs < HH) && (ws >= 0 && ws < WW);
            int hsc = v ? hs : 0, wsc = v ? ws : 0;
            const unsigned char* src = g_mid + ((size_t)((b*HH + hsc)*WW + wsc))*CH + ch*16;
            cp16(rb + r*RBSTRIDE + p*256 + ((ch ^ (p & 7)) << 4), src, v);
        }
    }
    auto loadB = [&](int t, int s) {
        unsigned bB = smem_u32(sm + 99840 + s*32768);
        const unsigned char* bs = g_wmc + ((size_t)(t*CH + nh*128))*CH;
        #pragma unroll
        for (int i = 0; i < 8; i++) {                 // 2048 chunks
            int idx = i*256 + tid;
            int o = idx >> 4, ch = idx & 15;
            cp16(bB + o*256 + ((ch ^ (o & 7)) << 4), bs + (size_t)o*CH + ch*16, true);
        }
    };
    loadB(0, 0);
    cp_commit();

    int acc[2][8][4];
    #pragma unroll
    for (int i = 0; i < 2; i++)
        #pragma unroll
        for (int j = 0; j < 8; j++)
            #pragma unroll
            for (int l = 0; l < 4; l++) acc[i][j][l] = 0;

    const int a_row = lane & 15;
    const int a_kx  = (lane >> 4) & 1;
    const int b_row = (lane & 7) + ((lane >> 4) & 1) * 8;
    const int b_kx  = (lane >> 3) & 1;

    for (int t = 0; t < 9; t++) {
        if (t < 8) loadB(t + 1, (t + 1) & 1);
        cp_commit();
        cp_wait<1>();
        __syncthreads();
        const int dh = t/3 - 1, dw = t%3 - 1;
        unsigned aB = smem_u32(sm) + (dh + 1)*RBSTRIDE;
        unsigned bB = smem_u32(sm + 99840 + (t & 1)*32768);
        const int pb = m0 + a_row + 1 + dw;           // p in [0,130)
        #pragma unroll
        for (int ks = 0; ks < 8; ks++) {
            unsigned af[2][4];
            #pragma unroll
            for (int mt = 0; mt < 2; mt++) {
                int p = pb + mt*16;
                ldsm4(af[mt][0], af[mt][1], af[mt][2], af[mt][3],
                      aB + p*256 + (((2*ks + a_kx) ^ (p & 7)) << 4));
            }
            #pragma unroll
            for (int bt = 0; bt < 4; bt++) {
                unsigned r0, r1, r2, r3;
                int o = n0 + bt*16 + b_row;
                ldsm4(r0, r1, r2, r3, bB + o*256 + (((2*ks + b_kx) ^ (o & 7)) << 4));
                #pragma unroll
                for (int mt = 0; mt < 2; mt++) {
                    mma8(acc[mt][2*bt],     af[mt][0], af[mt][1], af[mt][2], af[mt][3], r0, r1);
                    mma8(acc[mt][2*bt + 1], af[mt][0], af[mt][1], af[mt][2], af[mt][3], r2, r3);
                }
            }
        }
        __syncthreads();
    }
    cp_wait<0>();
    __syncthreads();

    // epilogue: bias + prelu, stage f32 [o 128][px pad 132], coalesced +x store
    float* st = (float*)sm;
    const float a2v = a2p[0];
    #pragma unroll
    for (int mt = 0; mt < 2; mt++)
        #pragma unroll
        for (int nt = 0; nt < 8; nt++)
            #pragma unroll
            for (int di = 0; di < 4; di++) {
                int px = m0 + mt*16 + (lane >> 2) + 8*(di >> 1);
                int ol = n0 + nt*8 + (lane & 3)*2 + (di & 1);
                float v = (float)acc[mt][nt][di] + __ldg(bc + nh*128 + ol);
                v = (v >= 0.f) ? v : a2v * v;
                st[ol*132 + px] = v;
            }
    __syncthreads();
    #pragma unroll
    for (int it = 0; it < 16; it++) {
        int e = it*256 + tid;                         // 4096 float4 slots
        int ol = e >> 5, q = e & 31;
        int og = nh*128 + ol;
        size_t gi = (((size_t)(b*CH + og))*HH + h)*WW + q*4;
        float4 v  = *(const float4*)(st + ol*132 + q*4);
        float4 xr = *(const float4*)(x + gi);
        v.x += xr.x; v.y += xr.y; v.z += xr.z; v.w += xr.w;
        *(float4*)(out + gi) = v;
    }
}

// ---------------------------------------------------------------------------
extern "C" void kernel_launch(void* const* d_in, const int* in_sizes, int n_in,
                              void* d_out, int out_size) {
    const float* x  = (const float*)d_in[0];
    const float* w1 = (const float*)d_in[1];
    const float* b1 = (const float*)d_in[2];
    const float* w2 = (const float*)d_in[3];
    const float* b2 = (const float*)d_in[4];
    const float* w3 = (const float*)d_in[5];
    const float* b3 = (const float*)d_in[6];
    const float* w4 = (const float*)d_in[7];
    const float* b4 = (const float*)d_in[8];
    const float* a1 = (const float*)d_in[9];
    const float* wc = (const float*)d_in[10];
    const float* bc = (const float*)d_in[11];
    const float* a2 = (const float*)d_in[12];
    float* out = (float*)d_out;

    static bool attr_done = false;
    if (!attr_done) {
        cudaFuncSetAttribute(branch_gemm, cudaFuncAttributeMaxDynamicSharedMemorySize, 98304);
        cudaFuncSetAttribute(main_gemm,   cudaFuncAttributeMaxDynamicSharedMemorySize, 165376);
        attr_done = true;
    }

    pack_acts<<<4096, 256>>>(x);
    pack_wts<<<896, 256>>>(w1, w2, w3, w4, wc);
    branch_gemm<<<4096, 256, 98304>>>(b1, b2, b3, b4, a1);
    main_gemm<<<2048, 256, 165376>>>(x, bc, a2, out);
}

// round 5
// speedup vs baseline: 1.9074x; 1.9074x over previous
#include <cuda_runtime.h>
#include <cstdint>

#define BB_ 8
#define CC_ 256
#define HH_ 128
#define WW_ 128
#define NPIX (BB_*HH_*WW_)   // 131072
#define HW_ (HH_*WW_)        // 16384

// Bit-packed scratch (allocation-free __device__ globals).
// Per pixel: 8 uint32 words (= 2 uint4); bit i of word wd = channel wd*32+i, 1 <=> value >= 0.
__device__ uint4 g_xbits[NPIX*2];       // 4 MB  binarized input
__device__ uint4 g_mbits[NPIX*2];       // 4 MB  binarized mid (concat of 4 branches)
__device__ uint4 g_wb  [4*5*64*2];      // branch weights: [br][k][o][2]  (tap-major for coalescing)
__device__ uint4 g_wcb [9*256*2];       // main weights:   [t][o][2]

__device__ __forceinline__ int pdot8(uint4 a0, uint4 a1, uint4 b0, uint4 b1) {
    return __popc(a0.x^b0.x) + __popc(a0.y^b0.y) + __popc(a0.z^b0.z) + __popc(a0.w^b0.w)
         + __popc(a1.x^b1.x) + __popc(a1.y^b1.y) + __popc(a1.z^b1.z) + __popc(a1.w^b1.w);
}
__device__ __forceinline__ int popc8w(uint4 a, uint4 b) {
    return __popc(a.x) + __popc(a.y) + __popc(a.z) + __popc(a.w)
         + __popc(b.x) + __popc(b.y) + __popc(b.z) + __popc(b.w);
}

// ---------------------------------------------------------------------------
// Pack binarized x into bits. thread = (word, pixel), pixel fastest (coalesced).
__global__ __launch_bounds__(256) void pack_x(const float* __restrict__ x) {
    int tid = blockIdx.x*256 + threadIdx.x;
    int wd  = tid >> 17;            // 0..7
    int pix = tid & (NPIX-1);
    int b   = pix >> 14;
    int hw  = pix & (HW_-1);
    const float* p = x + ((size_t)(b*CC_ + wd*32))*HW_ + hw;
    unsigned bits = 0;
    #pragma unroll
    for (int i = 0; i < 32; i++)
        if (p[(size_t)i*HW_] >= 0.f) bits |= (1u << i);
    ((unsigned*)g_xbits)[pix*8 + wd] = bits;
}

// ---------------------------------------------------------------------------
// Pack binarized weights into tap-major layouts. 28672 threads.
__global__ __launch_bounds__(256) void pack_w(
    const float* __restrict__ w1, const float* __restrict__ w2,
    const float* __restrict__ w3, const float* __restrict__ w4,
    const float* __restrict__ wc)
{
    int tid = blockIdx.x*256 + threadIdx.x;
    if (tid < 4*5*64*8) {
        int wd = tid & 7;
        int o  = (tid >> 3) & 63;
        int kk = tid >> 9;          // br*5 + k
        int k  = kk % 5, br = kk / 5;
        const float* src = (br==0) ? w1 : (br==1) ? w2 : (br==2) ? w3 : w4;
        unsigned bits = 0;
        #pragma unroll
        for (int i = 0; i < 32; i++) {
            int c = wd*32 + i;
            float v = src[(o*CC_ + c)*5 + k];
            if (v >= 0.f) bits |= (1u << i);
        }
        ((unsigned*)g_wb)[tid] = bits;      // index == (((br*5+k)*64+o)*8+wd)
    } else {
        int j = tid - 4*5*64*8;
        if (j < 9*256*8) {
            int wd = j & 7;
            int o  = (j >> 3) & 255;
            int t  = j >> 11;
            unsigned bits = 0;
            #pragma unroll
            for (int i = 0; i < 32; i++) {
                int c = wd*32 + i;
                float v = wc[(o*CC_ + c)*9 + t];
                if (v >= 0.f) bits |= (1u << i);
            }
            ((unsigned*)g_wcb)[j] = bits;   // index == ((t*256+o)*8+wd)
        }
    }
}

// ---------------------------------------------------------------------------
// Branch convs -> sign bits of prelu(concat). Block = 32-px row strip.
// 256 threads = 256 concat channels; warp w -> (br = w>>1, o = (w&1)*32+lane).
// Zero-padded halo, unconditional 5-tap accumulate, algebraic edge correction.
__global__ __launch_bounds__(256) void branch_conv(
    const float* __restrict__ b1, const float* __restrict__ b2,
    const float* __restrict__ b3, const float* __restrict__ b4,
    const float* __restrict__ a1p)
{
    __shared__ uint4 xt[9*40*2];    // rows h-4..h+4, cols w0-4..w0+35 (11.25 KB)
    const int bx = blockIdx.x, h = blockIdx.y, bb = blockIdx.z;
    const int w0 = bx*32;
    const int tid = threadIdx.x, warp = tid >> 5, lane = tid & 31;

    for (int i = tid; i < 9*40; i += 256) {
        int r = i / 40, c = i % 40;
        int hh = h - 4 + r, ww = w0 - 4 + c;
        uint4 v0 = make_uint4(0,0,0,0), v1 = v0;
        if ((unsigned)hh < HH_ && (unsigned)ww < WW_) {
            const uint4* s = g_xbits + ((bb*HH_ + hh)*WW_ + ww)*2;
            v0 = s[0]; v1 = s[1];
        }
        xt[i*2] = v0; xt[i*2+1] = v1;
    }
    __syncthreads();

    const int br = warp >> 1;
    const int o  = (warp & 1)*32 + lane;
    const int sh = (br >= 2) ? ((br == 2) ? 1 : 2) : 0;
    const int sw = (br <  2) ? ((br == 0) ? 1 : 2) : 0;
    const bool edge = (br < 2) ? (bx == 0 || bx == 3) : (h < 4 || h > 123);
    const float bias = ((br==0) ? b1 : (br==1) ? b2 : (br==2) ? b3 : b4)[o];
    const float a1 = a1p[0];
    unsigned* mout = (unsigned*)g_mbits + ((bb*HH_ + h)*WW_ + w0)*8 + warp;

    for (int ch = 0; ch < 4; ch++) {
        int acc[8];
        #pragma unroll
        for (int p = 0; p < 8; p++) acc[p] = 0;

        #pragma unroll
        for (int k = 0; k < 5; k++) {
            const uint4* wp = g_wb + ((br*5 + k)*64 + o)*2;
            uint4 wA = wp[0], wB = wp[1];
            int d = k - 2, dh = d*sh, dw = d*sw;
            int r = 4 + dh, cb = 4 + dw + ch*8;
            #pragma unroll
            for (int p = 0; p < 8; p++) {
                const uint4* s = xt + (r*40 + cb + p)*2;
                acc[p] += pdot8(s[0], s[1], wA, wB);
            }
        }
        if (edge) {
            #pragma unroll
            for (int k = 0; k < 5; k++) {
                const uint4* wp = g_wb + ((br*5 + k)*64 + o)*2;
                int pw = popc8w(wp[0], wp[1]);
                int d = k - 2, dh = d*sh, dw = d*sw;
                int hh = h + dh;
                bool hInv = ((unsigned)hh >= HH_);
                #pragma unroll
                for (int p = 0; p < 8; p++) {
                    int ww = w0 + ch*8 + p + dw;
                    if (hInv || (unsigned)ww >= WW_) acc[p] += 128 - pw;
                }
            }
        }
        #pragma unroll
        for (int p = 0; p < 8; p++) {
            float v  = (float)(1280 - 2*acc[p]) + bias;
            float pr = (v >= 0.f) ? v : a1*v;
            unsigned m = __ballot_sync(0xffffffffu, pr >= 0.f);
            if (lane == 0) mout[(ch*8 + p)*8] = m;
        }
    }
}

// ---------------------------------------------------------------------------
// Main 3x3 conv + bias + prelu + residual. Block = 32-px row strip.
// 256 threads = 256 out channels. Zero-padded halo, unconditional 9-tap
// accumulate, algebraic edge correction, direct 128B-line f32 stores.
__global__ __launch_bounds__(256) void main_conv(
    const float* __restrict__ x, const float* __restrict__ bc,
    const float* __restrict__ a2p, float* __restrict__ out)
{
    __shared__ uint4 xt[3*34*2];    // rows h-1..h+1, cols w0-1..w0+32 (3.3 KB)
    const int bx = blockIdx.x, h = blockIdx.y, bb = blockIdx.z;
    const int w0 = bx*32;
    const int tid = threadIdx.x;    // = out channel

    for (int i = tid; i < 3*34; i += 256) {
        int r = i / 34, c = i % 34;
        int hh = h - 1 + r, ww = w0 - 1 + c;
        uint4 v0 = make_uint4(0,0,0,0), v1 = v0;
        if ((unsigned)hh < HH_ && (unsigned)ww < WW_) {
            const uint4* s = g_mbits + ((bb*HH_ + hh)*WW_ + ww)*2;
            v0 = s[0]; v1 = s[1];
        }
        xt[i*2] = v0; xt[i*2+1] = v1;
    }
    __syncthreads();

    const bool edge = (h == 0) | (h == 127) | (bx == 0) | (bx == 3);
    const float a2 = a2p[0];
    const float bias = bc[tid];
    const size_t gbase = (((size_t)bb*CC_ + tid)*HH_ + h)*WW_ + w0;

    for (int ch = 0; ch < 4; ch++) {
        int acc[8];
        #pragma unroll
        for (int p = 0; p < 8; p++) acc[p] = 0;

        #pragma unroll
        for (int t = 0; t < 9; t++) {
            const uint4* wp = g_wcb + (t*256 + tid)*2;
            uint4 wA = wp[0], wB = wp[1];
            int r = t/3, dc = t%3;
            #pragma unroll
            for (int p = 0; p < 8; p++) {
                const uint4* s = xt + (r*34 + ch*8 + p + dc)*2;
                acc[p] += pdot8(s[0], s[1], wA, wB);
            }
        }
        if (edge) {
            #pragma unroll
            for (int t = 0; t < 9; t++) {
                const uint4* wp = g_wcb + (t*256 + tid)*2;
                int pw = popc8w(wp[0], wp[1]);
                int hh = h + t/3 - 1, dw = t%3 - 1;
                bool hInv = ((unsigned)hh >= HH_);
                #pragma unroll
                for (int p = 0; p < 8; p++) {
                    int ww = w0 + ch*8 + p + dw;
                    if (hInv || (unsigned)ww >= WW_) acc[p] += 128 - pw;
                }
            }
        }
        // each lane owns its full 128B NCHW line: direct float4 residual + store
        #pragma unroll
        for (int q = 0; q < 2; q++) {
            float4 xr = *(const float4*)(x + gbase + ch*8 + q*4);
            float4 o4;
            float v0 = (float)(2304 - 2*acc[q*4+0]) + bias; v0 = (v0 >= 0.f) ? v0 : a2*v0;
            float v1 = (float)(2304 - 2*acc[q*4+1]) + bias; v1 = (v1 >= 0.f) ? v1 : a2*v1;
            float v2 = (float)(2304 - 2*acc[q*4+2]) + bias; v2 = (v2 >= 0.f) ? v2 : a2*v2;
            float v3 = (float)(2304 - 2*acc[q*4+3]) + bias; v3 = (v3 >= 0.f) ? v3 : a2*v3;
            o4.x = v0 + xr.x; o4.y = v1 + xr.y; o4.z = v2 + xr.z; o4.w = v3 + xr.w;
            *(float4*)(out + gbase + ch*8 + q*4) = o4;
        }
    }
}

// ---------------------------------------------------------------------------
extern "C" void kernel_launch(void* const* d_in, const int* in_sizes, int n_in,
                              void* d_out, int out_size) {
    const float* x  = (const float*)d_in[0];
    const float* w1 = (const float*)d_in[1];
    const float* b1 = (const float*)d_in[2];
    const float* w2 = (const float*)d_in[3];
    const float* b2 = (const float*)d_in[4];
    const float* w3 = (const float*)d_in[5];
    const float* b3 = (const float*)d_in[6];
    const float* w4 = (const float*)d_in[7];
    const float* b4 = (const float*)d_in[8];
    const float* a1 = (const float*)d_in[9];
    const float* wc = (const float*)d_in[10];
    const float* bc = (const float*)d_in[11];
    const float* a2 = (const float*)d_in[12];
    float* out = (float*)d_out;

    pack_x<<<4096, 256>>>(x);
    pack_w<<<112, 256>>>(w1, w2, w3, w4, wc);
    branch_conv<<<dim3(4,128,8), 256>>>(b1, b2, b3, b4, a1);
    main_conv<<<dim3(4,128,8), 256>>>(x, bc, a2, out);
}

// round 6
// speedup vs baseline: 1.9763x; 1.0361x over previous
#include <cuda_runtime.h>
#include <cstdint>

#define BB_ 8
#define CC_ 256
#define HH_ 128
#define WW_ 128
#define NPIX (BB_*HH_*WW_)   // 131072
#define HW_ (HH_*WW_)        // 16384

// Bit-packed scratch (allocation-free __device__ globals).
// Per pixel: 8 uint32 words (= 2 uint4); bit i of word wd = channel wd*32+i, 1 <=> value >= 0.
__device__ uint4 g_xbits[NPIX*2];       // 4 MB  binarized input
__device__ uint4 g_mbits[NPIX*2];       // 4 MB  binarized mid (concat of 4 branches)
__device__ uint4 g_wb  [4*5*64*2];      // branch weights: [br][k][o][2]  (tap-major)
__device__ uint4 g_wcb [9*256*2];       // main weights:   [t][o][2]

__device__ __forceinline__ int pdot8(uint4 a0, uint4 a1, uint4 b0, uint4 b1) {
    return __popc(a0.x^b0.x) + __popc(a0.y^b0.y) + __popc(a0.z^b0.z) + __popc(a0.w^b0.w)
         + __popc(a1.x^b1.x) + __popc(a1.y^b1.y) + __popc(a1.z^b1.z) + __popc(a1.w^b1.w);
}
__device__ __forceinline__ int popc8w(uint4 a, uint4 b) {
    return __popc(a.x) + __popc(a.y) + __popc(a.z) + __popc(a.w)
         + __popc(b.x) + __popc(b.y) + __popc(b.z) + __popc(b.w);
}

// ---------------------------------------------------------------------------
// Pack binarized x into bits. thread = (word, pixel), pixel fastest (coalesced).
__global__ __launch_bounds__(256) void pack_x(const float* __restrict__ x) {
    int tid = blockIdx.x*256 + threadIdx.x;
    int wd  = tid >> 17;            // 0..7
    int pix = tid & (NPIX-1);
    int b   = pix >> 14;
    int hw  = pix & (HW_-1);
    const float* p = x + ((size_t)(b*CC_ + wd*32))*HW_ + hw;
    unsigned bits = 0;
    #pragma unroll
    for (int i = 0; i < 32; i++)
        if (p[(size_t)i*HW_] >= 0.f) bits |= (1u << i);
    ((unsigned*)g_xbits)[pix*8 + wd] = bits;
}

// ---------------------------------------------------------------------------
// Pack binarized weights into tap-major layouts.
__global__ __launch_bounds__(256) void pack_w(
    const float* __restrict__ w1, const float* __restrict__ w2,
    const float* __restrict__ w3, const float* __restrict__ w4,
    const float* __restrict__ wc)
{
    int tid = blockIdx.x*256 + threadIdx.x;
    if (tid < 4*5*64*8) {
        int wd = tid & 7;
        int o  = (tid >> 3) & 63;
        int kk = tid >> 9;          // br*5 + k
        int k  = kk % 5, br = kk / 5;
        const float* src = (br==0) ? w1 : (br==1) ? w2 : (br==2) ? w3 : w4;
        unsigned bits = 0;
        #pragma unroll
        for (int i = 0; i < 32; i++) {
            int c = wd*32 + i;
            float v = src[(o*CC_ + c)*5 + k];
            if (v >= 0.f) bits |= (1u << i);
        }
        ((unsigned*)g_wb)[tid] = bits;      // (((br*5+k)*64+o)*8+wd)
    } else {
        int j = tid - 4*5*64*8;
        if (j < 9*256*8) {
            int wd = j & 7;
            int o  = (j >> 3) & 255;
            int t  = j >> 11;
            unsigned bits = 0;
            #pragma unroll
            for (int i = 0; i < 32; i++) {
                int c = wd*32 + i;
                float v = wc[(o*CC_ + c)*9 + t];
                if (v >= 0.f) bits |= (1u << i);
            }
            ((unsigned*)g_wcb)[j] = bits;   // ((t*256+o)*8+wd)
        }
    }
}

// ---------------------------------------------------------------------------
// Branch convs -> sign bits of prelu(concat). Block = 32-px row strip, 512 thr.
// tid = half*256 + ch: half picks 16-px sub-strip, ch = concat channel.
// Warps 0-7 (half 0) and 8-15 (half 1) each span 32 consecutive channels -> ballot.
// Zero-padded halo, unconditional taps, algebraic edge correction.
__global__ __launch_bounds__(512, 2) void branch_conv(
    const float* __restrict__ b1, const float* __restrict__ b2,
    const float* __restrict__ b3, const float* __restrict__ b4,
    const float* __restrict__ a1p)
{
    __shared__ uint4 xt[9*40*2];    // rows h-4..h+4, cols w0-4..w0+35 (11.25 KB)
    const int bx = blockIdx.x, h = blockIdx.y, bb = blockIdx.z;
    const int w0 = bx*32;
    const int tid = threadIdx.x, lane = tid & 31;
    const int ch = tid & 255, half = tid >> 8, px0 = half*16;

    for (int i = tid; i < 9*40; i += 512) {
        int r = i / 40, c = i % 40;
        int hh = h - 4 + r, ww = w0 - 4 + c;
        uint4 v0 = make_uint4(0,0,0,0), v1 = v0;
        if ((unsigned)hh < HH_ && (unsigned)ww < WW_) {
            const uint4* s = g_xbits + ((bb*HH_ + hh)*WW_ + ww)*2;
            v0 = s[0]; v1 = s[1];
        }
        xt[i*2] = v0; xt[i*2+1] = v1;
    }
    __syncthreads();

    const int br = ch >> 6;
    const int o  = ch & 63;
    const int sh = (br >= 2) ? ((br == 2) ? 1 : 2) : 0;
    const int sw = (br <  2) ? ((br == 0) ? 1 : 2) : 0;
    const bool edge = (br < 2) ? (bx == 0 || bx == 3) : (h < 4 || h > 123);

    int acc[16];
    #pragma unroll
    for (int p = 0; p < 16; p++) acc[p] = 0;

    #pragma unroll 1
    for (int k = 0; k < 5; k++) {
        const uint4* wp = g_wb + ((br*5 + k)*64 + o)*2;
        uint4 wA = wp[0], wB = wp[1];
        int d = k - 2;
        const uint4* s = xt + (((4 + d*sh)*40) + 4 + d*sw + px0)*2;
        #pragma unroll
        for (int p = 0; p < 16; p++)
            acc[p] += pdot8(s[2*p], s[2*p+1], wA, wB);
    }
    if (edge) {
        #pragma unroll 1
        for (int k = 0; k < 5; k++) {
            const uint4* wp = g_wb + ((br*5 + k)*64 + o)*2;
            int pw = popc8w(wp[0], wp[1]);
            int d = k - 2, dh = d*sh, dw = d*sw;
            bool hInv = ((unsigned)(h + dh) >= HH_);
            #pragma unroll
            for (int p = 0; p < 16; p++) {
                int ww = w0 + px0 + p + dw;
                if (hInv || (unsigned)ww >= WW_) acc[p] += 128 - pw;
            }
        }
    }

    const float bias = ((br==0) ? b1 : (br==1) ? b2 : (br==2) ? b3 : b4)[o];
    const float a1 = a1p[0];
    unsigned* mout = (unsigned*)g_mbits + ((bb*HH_ + h)*WW_ + w0 + px0)*8 + (ch >> 5);
    #pragma unroll
    for (int p = 0; p < 16; p++) {
        float v  = (float)(1280 - 2*acc[p]) + bias;
        float pr = (v >= 0.f) ? v : a1*v;
        unsigned m = __ballot_sync(0xffffffffu, pr >= 0.f);
        if (lane == 0) mout[p*8] = m;
    }
}

// ---------------------------------------------------------------------------
// Main 3x3 conv + bias + prelu + residual. Block = 32-px row strip, 512 thr.
// tid = half*256 + oc. Zero-padded halo, tap-outer loop with unroll 1 so only
// one tap's weights (8 regs) are live; 16 accumulators per thread.
__global__ __launch_bounds__(512, 2) void main_conv(
    const float* __restrict__ x, const float* __restrict__ bc,
    const float* __restrict__ a2p, float* __restrict__ out)
{
    __shared__ uint4 xt[3*34*2];    // rows h-1..h+1, cols w0-1..w0+32 (3.3 KB)
    const int bx = blockIdx.x, h = blockIdx.y, bb = blockIdx.z;
    const int w0 = bx*32;
    const int tid = threadIdx.x;
    const int oc = tid & 255, half = tid >> 8, px0 = half*16;

    for (int i = tid; i < 3*34; i += 512) {
        int r = i / 34, c = i % 34;
        int hh = h - 1 + r, ww = w0 - 1 + c;
        uint4 v0 = make_uint4(0,0,0,0), v1 = v0;
        if ((unsigned)hh < HH_ && (unsigned)ww < WW_) {
            const uint4* s = g_mbits + ((bb*HH_ + hh)*WW_ + ww)*2;
            v0 = s[0]; v1 = s[1];
        }
        xt[i*2] = v0; xt[i*2+1] = v1;
    }
    __syncthreads();

    int acc[16];
    #pragma unroll
    for (int p = 0; p < 16; p++) acc[p] = 0;

    #pragma unroll 1
    for (int t = 0; t < 9; t++) {
        const uint4* wp = g_wcb + (t*256 + oc)*2;
        uint4 wA = wp[0], wB = wp[1];
        const uint4* s = xt + ((t/3)*34 + px0 + (t%3))*2;
        #pragma unroll
        for (int p = 0; p < 16; p++)
            acc[p] += pdot8(s[2*p], s[2*p+1], wA, wB);
    }
    const bool edge = (h == 0) | (h == 127) | (bx == 0) | (bx == 3);
    if (edge) {
        #pragma unroll 1
        for (int t = 0; t < 9; t++) {
            const uint4* wp = g_wcb + (t*256 + oc)*2;
            int pw = popc8w(wp[0], wp[1]);
            bool hInv = ((unsigned)(h + t/3 - 1) >= HH_);
            int dw = t%3 - 1;
            #pragma unroll
            for (int p = 0; p < 16; p++) {
                int ww = w0 + px0 + p + dw;
                if (hInv || (unsigned)ww >= WW_) acc[p] += 128 - pw;
            }
        }
    }

    const float a2 = a2p[0];
    const float bias = bc[oc];
    const size_t gbase = (((size_t)bb*CC_ + oc)*HH_ + h)*WW_ + w0 + px0;
    #pragma unroll
    for (int q = 0; q < 4; q++) {
        float4 xr = *(const float4*)(x + gbase + q*4);
        float4 o4;
        float v0 = (float)(2304 - 2*acc[q*4+0]) + bias; v0 = (v0 >= 0.f) ? v0 : a2*v0;
        float v1 = (float)(2304 - 2*acc[q*4+1]) + bias; v1 = (v1 >= 0.f) ? v1 : a2*v1;
        float v2 = (float)(2304 - 2*acc[q*4+2]) + bias; v2 = (v2 >= 0.f) ? v2 : a2*v2;
        float v3 = (float)(2304 - 2*acc[q*4+3]) + bias; v3 = (v3 >= 0.f) ? v3 : a2*v3;
        o4.x = v0 + xr.x; o4.y = v1 + xr.y; o4.z = v2 + xr.z; o4.w = v3 + xr.w;
        *(float4*)(out + gbase + q*4) = o4;
    }
}

// ---------------------------------------------------------------------------
extern "C" void kernel_launch(void* const* d_in, const int* in_sizes, int n_in,
                              void* d_out, int out_size) {
    const float* x  = (const float*)d_in[0];
    const float* w1 = (const float*)d_in[1];
    const float* b1 = (const float*)d_in[2];
    const float* w2 = (const float*)d_in[3];
    const float* b2 = (const float*)d_in[4];
    const float* w3 = (const float*)d_in[5];
    const float* b3 = (const float*)d_in[6];
    const float* w4 = (const float*)d_in[7];
    const float* b4 = (const float*)d_in[8];
    const float* a1 = (const float*)d_in[9];
    const float* wc = (const float*)d_in[10];
    const float* bc = (const float*)d_in[11];
    const float* a2 = (const float*)d_in[12];
    float* out = (float*)d_out;

    pack_x<<<4096, 256>>>(x);
    pack_w<<<112, 256>>>(w1, w2, w3, w4, wc);
    branch_conv<<<dim3(4,128,8), 512>>>(b1, b2, b3, b4, a1);
    main_conv<<<dim3(4,128,8), 512>>>(x, bc, a2, out);
}